// round 6
// baseline (speedup 1.0000x reference)
#include <cuda_runtime.h>

// DEER LIF wavefront solver: 4 balanced time-chunks (all blocks run 304 steps),
// 2-lane split of the 10 iteration rows (5 rows/thread), paired rcp (5 EX2 +
// 3 RCP per thread-step instead of 5+5).

#define T_LEN   1024
#define NE      16384
#define NCHUNKS 4
#define SPAN    304      // steps per block (halo+write, uniform)
#define STRIDE  240      // write span of chunks 1..3
#define HALO    64
#define PF      4
#define BLOCK   128
#define RPT     5

// ax = (2.8 - 4h)*log2(e)
#define C_NEG (-5.770780163555852f)
#define C_POS ( 4.039546114489096f)

__device__ __forceinline__ float ex2f(float a) {
    float r; asm("ex2.approx.ftz.f32 %0, %1;" : "=f"(r) : "f"(a)); return r;
}
__device__ __forceinline__ float rcpf(float a) {
    float r; asm("rcp.approx.ftz.f32 %0, %1;" : "=f"(r) : "f"(a)); return r;
}

template <bool STORE>
__device__ __forceinline__ void lif_step(int t, float xt,
                                         float* __restrict__ q, float& p0,
                                         bool upper,
                                         float* __restrict__ spike_out,
                                         float* __restrict__ y_out, int e)
{
    // y5[t-1] from the lower half-warp (payload ignored in the other direction)
    const float y5x = __shfl_xor_sync(0xffffffffu, q[RPT - 1], 16);
    const float hx  = 0.5f * xt;

    float ys[RPT];
    ys[0] = upper ? y5x : p0;
#pragma unroll
    for (int j = 1; j < RPT; ++j) ys[j] = q[j - 1];

    float h[RPT], w[RPT];
#pragma unroll
    for (int j = 0; j < RPT; ++j) {
        h[j] = fmaf(0.5f, ys[j], hx);
        w[j] = 1.0f + ex2f(fmaf(h[j], C_NEG, C_POS));
    }

    // paired reciprocals: 3 RCP for 5 sigmoids
    float s[RPT];
    const float r43 = rcpf(w[4] * w[3]);
    s[4] = r43 * w[3];
    s[3] = r43 * w[4];
    const float r21 = rcpf(w[2] * w[1]);
    s[2] = r21 * w[1];
    s[1] = r21 * w[2];
    s[0] = rcpf(w[0]);

#pragma unroll
    for (int j = 0; j < RPT; ++j) {
        const float qq = fmaf(-s[j], s[j], s[j]);   // s*(1-s)
        const float a  = fmaf(qq, -2.0f, 0.5f);     // 0.5*(1-sg)
        q[j] = fmaf(a, q[j] - ys[j], h[j]);         // a*y_prev + (h - a*ys)
    }

    // warmstart row (nonzero only for t<2; uniform across warp)
    p0 = (t < 2) ? fmaf(0.5f, p0, hx) : 0.0f;

    if (STORE && upper) {
        const float yv = q[RPT - 1];                // y_10
        const size_t o = (size_t)t * NE + e;
        y_out[o]     = yv;
        spike_out[o] = (yv >= 0.7f) ? 1.0f : 0.0f;
    }
}

__global__ __launch_bounds__(BLOCK, 7)
void deer_lif_kernel(const float* __restrict__ x,
                     const float* __restrict__ v_init,
                     float* __restrict__ out)
{
    const int lane   = threadIdx.x & 31;
    const int sub    = lane & 15;
    const bool upper = lane >= 16;
    const int warp   = threadIdx.x >> 5;
    const int e      = blockIdx.x * 64 + warp * 16 + sub;

    const int chunk   = blockIdx.y;
    const int t_begin = STRIDE * chunk;              // 0,240,480,720
    const int t_end   = t_begin + SPAN;              // 304,544,784,1024
    const int t_write = (chunk == 0) ? 0 : t_begin + HALO;

    const float init = (chunk == 0) ? v_init[e] : 0.0f;
    float q[RPT];
#pragma unroll
    for (int j = 0; j < RPT; ++j) q[j] = init;
    float p0 = init;

    float* __restrict__ spike_out = out;
    float* __restrict__ y_out     = out + (size_t)T_LEN * NE;
    const float* __restrict__ xp  = x + e;

    float xb[PF];
#pragma unroll
    for (int i = 0; i < PF; ++i)
        xb[i] = xp[(size_t)(t_begin + i) * NE];

    // halo warm-in (empty for chunk 0)
#pragma unroll 4
    for (int t = t_begin; t < t_write; ++t) {
        const float xt = xb[0];
#pragma unroll
        for (int i = 0; i < PF - 1; ++i) xb[i] = xb[i + 1];
        const int tp = t + PF;
        xb[PF - 1] = (tp < T_LEN) ? xp[(size_t)tp * NE] : 0.0f;
        lif_step<false>(t, xt, q, p0, upper, spike_out, y_out, e);
    }

    // main span
#pragma unroll 4
    for (int t = t_write; t < t_end; ++t) {
        const float xt = xb[0];
#pragma unroll
        for (int i = 0; i < PF - 1; ++i) xb[i] = xb[i + 1];
        const int tp = t + PF;
        xb[PF - 1] = (tp < T_LEN) ? xp[(size_t)tp * NE] : 0.0f;
        lif_step<true>(t, xt, q, p0, upper, spike_out, y_out, e);
    }
}

extern "C" void kernel_launch(void* const* d_in, const int* in_sizes, int n_in,
                              void* d_out, int out_size)
{
    const float* x      = (const float*)d_in[0];   // (T,B,F) float32
    const float* v_init = (const float*)d_in[1];   // (B,F)   float32
    float* out          = (float*)d_out;           // [spike; y]

    dim3 grid(NE / 64, NCHUNKS);                   // (256, 4)
    deer_lif_kernel<<<grid, BLOCK>>>(x, v_init, out);
}